// round 1
// baseline (speedup 1.0000x reference)
#include <cuda_runtime.h>
#include <cuda_bf16.h>

// ---------------------------------------------------------------------------
// W-MSA: windowed multi-head self-attention (Swin block)
// B=16, C=384, H=W=64, window 8x8 (N=64), heads=12, hd=32, B_=1024 windows.
// Strategy: tf32 mma.sync GEMMs for QKV + proj; fp32 SIMT fused attention.
// ---------------------------------------------------------------------------

#define NWIN   1024
#define NHEAD  12
#define HD     32
#define NTOK   64      // tokens per window
#define CDIM   384

// Scratch (device globals; allocation-free rule)
__device__ float g_q[NWIN * NHEAD * NTOK * HD];   // [win][head][t][d], pre-scaled
__device__ float g_k[NWIN * NHEAD * NTOK * HD];
__device__ float g_v[NWIN * NHEAD * NTOK * HD];
__device__ float g_ao[NWIN * NTOK * CDIM];        // attention out, [token][c]

__device__ __forceinline__ unsigned f2tf32(float f) {
    unsigned u;
    asm("cvt.rna.tf32.f32 %0, %1;" : "=r"(u) : "f"(f));
    return u;
}

__device__ __forceinline__ void mma_tf32(float& c0, float& c1, float& c2, float& c3,
                                         unsigned a0, unsigned a1, unsigned a2, unsigned a3,
                                         unsigned b0, unsigned b1) {
    asm volatile(
        "mma.sync.aligned.m16n8k8.row.col.f32.tf32.tf32.f32 "
        "{%0,%1,%2,%3}, {%4,%5,%6,%7}, {%8,%9}, {%0,%1,%2,%3};\n"
        : "+f"(c0), "+f"(c1), "+f"(c2), "+f"(c3)
        : "r"(a0), "r"(a1), "r"(a2), "r"(a3), "r"(b0), "r"(b1));
}

// ---------------------------------------------------------------------------
// Kernel 1: QKV = gather(x) @ qkv_w^T + qkv_b
// Tile: BM=128 (2 windows), BN=128, BK=32. 256 threads = 8 warps (2M x 4N).
// Warp tile 64x32 -> 4 m16 tiles x 4 n8 tiles.
// ---------------------------------------------------------------------------
__global__ __launch_bounds__(256) void qkv_kernel(const float* __restrict__ x,
                                                  const float* __restrict__ qkv_w,
                                                  const float* __restrict__ qkv_b) {
    __shared__ unsigned sX[128 * 36];  // [row][k], pad 36 -> conflict-free frags
    __shared__ unsigned sW[128 * 36];  // [o][k]

    const int tid  = threadIdx.x;
    const int warp = tid >> 5, lane = tid & 31;
    const int g = lane >> 2, tg = lane & 3;
    const int warpM = warp >> 2;   // 0..1 (64 rows each)
    const int warpN = warp & 3;    // 0..3 (32 cols each)

    const int pair  = blockIdx.y;        // 0..511 (2 windows per CTA)
    const int obase = blockIdx.x * 128;  // 0..1151
    const int wb0   = pair * 2;

    float acc[4][4][4];
#pragma unroll
    for (int i = 0; i < 4; i++)
#pragma unroll
        for (int j = 0; j < 4; j++)
#pragma unroll
            for (int e = 0; e < 4; e++) acc[i][j][e] = 0.f;

    for (int kc = 0; kc < 12; kc++) {
        const int k0 = kc * 32;
        // --- load X tile (gather from NCHW) ---
#pragma unroll
        for (int i = tid; i < 4096; i += 256) {
            int kk = i >> 7, r = i & 127;
            int wb = wb0 + (r >> 6);
            int tt = r & 63;
            int b = wb >> 6, wy = (wb >> 3) & 7, wx = wb & 7;
            int h = wy * 8 + (tt >> 3), w = wx * 8 + (tt & 7);
            float v = x[(b * CDIM + k0 + kk) * 4096 + h * 64 + w];
            sX[r * 36 + kk] = f2tf32(v);
        }
        // --- load W tile (row-major, k contiguous) ---
#pragma unroll
        for (int i = tid; i < 1024; i += 256) {
            int row = i >> 3, kq = i & 7;
            const float4 v4 = *(const float4*)(qkv_w + (obase + row) * CDIM + k0 + kq * 4);
            unsigned* p = &sW[row * 36 + kq * 4];
            p[0] = f2tf32(v4.x); p[1] = f2tf32(v4.y);
            p[2] = f2tf32(v4.z); p[3] = f2tf32(v4.w);
        }
        __syncthreads();

#pragma unroll
        for (int ks = 0; ks < 4; ks++) {
            const int ko = ks * 8;
            unsigned a[4][4], bf[4][2];
#pragma unroll
            for (int mt = 0; mt < 4; mt++) {
                int rb = warpM * 64 + mt * 16;
                const unsigned* base = &sX[(rb + g) * 36 + ko + tg];
                a[mt][0] = base[0];
                a[mt][1] = base[8 * 36];
                a[mt][2] = base[4];
                a[mt][3] = base[8 * 36 + 4];
            }
#pragma unroll
            for (int nt = 0; nt < 4; nt++) {
                int nb = warpN * 32 + nt * 8;
                const unsigned* base = &sW[(nb + g) * 36 + ko + tg];
                bf[nt][0] = base[0];
                bf[nt][1] = base[4];
            }
#pragma unroll
            for (int mt = 0; mt < 4; mt++)
#pragma unroll
                for (int nt = 0; nt < 4; nt++)
                    mma_tf32(acc[mt][nt][0], acc[mt][nt][1], acc[mt][nt][2], acc[mt][nt][3],
                             a[mt][0], a[mt][1], a[mt][2], a[mt][3], bf[nt][0], bf[nt][1]);
        }
        __syncthreads();
    }

    // --- epilogue: bias, fold softmax scale into Q, scatter to q/k/v ---
    const float SCALE = 0.17677669529663687f;  // 1/sqrt(32)
#pragma unroll
    for (int mt = 0; mt < 4; mt++) {
#pragma unroll
        for (int nt = 0; nt < 4; nt++) {
            int row0 = warpM * 64 + mt * 16 + g;
            int col0 = warpN * 32 + nt * 8 + tg * 2;
#pragma unroll
            for (int e = 0; e < 4; e++) {
                int row = row0 + ((e >= 2) ? 8 : 0);
                int col = col0 + (e & 1);
                int o = obase + col;
                float v = acc[mt][nt][e] + qkv_b[o];
                int which = o / CDIM;
                int rem = o - which * CDIM;
                int head = rem >> 5, d = rem & 31;
                int wb = wb0 + (row >> 6), tt = row & 63;
                if (which == 0) v *= SCALE;
                float* dst = (which == 0) ? g_q : ((which == 1) ? g_k : g_v);
                dst[((wb * NHEAD + head) * NTOK + tt) * HD + d] = v;
            }
        }
    }
}

// ---------------------------------------------------------------------------
// Kernel 2: per-(window, head) attention.  64 threads, thread t owns query row t.
// S kept in registers (fully unrolled), K/V broadcast from smem.
// ---------------------------------------------------------------------------
__global__ __launch_bounds__(64) void attn_kernel(const float* __restrict__ rpb,
                                                  const int* __restrict__ rel) {
    __shared__ float sK[NTOK * HD];
    __shared__ float sV[NTOK * HD];
    const int head = blockIdx.x;   // 0..11
    const int wb   = blockIdx.y;   // 0..1023
    const int t    = threadIdx.x;  // 0..63

    const int base = (wb * NHEAD + head) * NTOK * HD;
    const float4* kp = (const float4*)(g_k + base);
    const float4* vp = (const float4*)(g_v + base);
#pragma unroll
    for (int i = t; i < NTOK * HD / 4; i += 64) {
        ((float4*)sK)[i] = kp[i];
        ((float4*)sV)[i] = vp[i];
    }

    float q[HD];
    const float4* qp = (const float4*)(g_q + base + t * HD);
#pragma unroll
    for (int i = 0; i < 8; i++) {
        float4 v = qp[i];
        q[i * 4] = v.x; q[i * 4 + 1] = v.y; q[i * 4 + 2] = v.z; q[i * 4 + 3] = v.w;
    }
    __syncthreads();

    const int* ri = rel + t * NTOK;
    float S[NTOK];
#pragma unroll
    for (int m = 0; m < NTOK; m++) {
        float acc = rpb[ri[m] * NHEAD + head];  // bias(t, m)
#pragma unroll
        for (int kk = 0; kk < HD; kk++) acc = fmaf(q[kk], sK[m * HD + kk], acc);
        S[m] = acc;
    }

    float mx = S[0];
#pragma unroll
    for (int m = 1; m < NTOK; m++) mx = fmaxf(mx, S[m]);
    float sum = 0.f;
#pragma unroll
    for (int m = 0; m < NTOK; m++) { S[m] = __expf(S[m] - mx); sum += S[m]; }
    const float inv = 1.0f / sum;

    float out[HD];
#pragma unroll
    for (int d = 0; d < HD; d++) out[d] = 0.f;
#pragma unroll
    for (int m = 0; m < NTOK; m++) {
        float p = S[m];
#pragma unroll
        for (int d = 0; d < HD; d++) out[d] = fmaf(p, sV[m * HD + d], out[d]);
    }

    float* dst = g_ao + (wb * NTOK + t) * CDIM + head * HD;
#pragma unroll
    for (int d = 0; d < HD; d += 4) {
        float4 v = make_float4(out[d] * inv, out[d + 1] * inv, out[d + 2] * inv, out[d + 3] * inv);
        *(float4*)(dst + d) = v;
    }
}

// ---------------------------------------------------------------------------
// Kernel 3: out = g_ao @ proj_w^T + proj_b, scattered back to NCHW.
// Same MMA skeleton as kernel 1 (A rows are contiguous tokens).
// ---------------------------------------------------------------------------
__global__ __launch_bounds__(256) void proj_kernel(const float* __restrict__ pw,
                                                   const float* __restrict__ pb,
                                                   float* __restrict__ out) {
    __shared__ unsigned sA[128 * 36];
    __shared__ unsigned sW[128 * 36];

    const int tid  = threadIdx.x;
    const int warp = tid >> 5, lane = tid & 31;
    const int g = lane >> 2, tg = lane & 3;
    const int warpM = warp >> 2;
    const int warpN = warp & 3;

    const int pair  = blockIdx.y;        // 0..511
    const int obase = blockIdx.x * 128;  // 0..383
    const int wb0   = pair * 2;

    float acc[4][4][4];
#pragma unroll
    for (int i = 0; i < 4; i++)
#pragma unroll
        for (int j = 0; j < 4; j++)
#pragma unroll
            for (int e = 0; e < 4; e++) acc[i][j][e] = 0.f;

    for (int kc = 0; kc < 12; kc++) {
        const int k0 = kc * 32;
#pragma unroll
        for (int i = tid; i < 1024; i += 256) {
            int row = i >> 3, kq = i & 7;
            const float4 v4 = *(const float4*)(g_ao + (pair * 128 + row) * CDIM + k0 + kq * 4);
            unsigned* p = &sA[row * 36 + kq * 4];
            p[0] = f2tf32(v4.x); p[1] = f2tf32(v4.y);
            p[2] = f2tf32(v4.z); p[3] = f2tf32(v4.w);
        }
#pragma unroll
        for (int i = tid; i < 1024; i += 256) {
            int row = i >> 3, kq = i & 7;
            const float4 v4 = *(const float4*)(pw + (obase + row) * CDIM + k0 + kq * 4);
            unsigned* p = &sW[row * 36 + kq * 4];
            p[0] = f2tf32(v4.x); p[1] = f2tf32(v4.y);
            p[2] = f2tf32(v4.z); p[3] = f2tf32(v4.w);
        }
        __syncthreads();

#pragma unroll
        for (int ks = 0; ks < 4; ks++) {
            const int ko = ks * 8;
            unsigned a[4][4], bf[4][2];
#pragma unroll
            for (int mt = 0; mt < 4; mt++) {
                int rb = warpM * 64 + mt * 16;
                const unsigned* base = &sA[(rb + g) * 36 + ko + tg];
                a[mt][0] = base[0];
                a[mt][1] = base[8 * 36];
                a[mt][2] = base[4];
                a[mt][3] = base[8 * 36 + 4];
            }
#pragma unroll
            for (int nt = 0; nt < 4; nt++) {
                int nb = warpN * 32 + nt * 8;
                const unsigned* base = &sW[(nb + g) * 36 + ko + tg];
                bf[nt][0] = base[0];
                bf[nt][1] = base[4];
            }
#pragma unroll
            for (int mt = 0; mt < 4; mt++)
#pragma unroll
                for (int nt = 0; nt < 4; nt++)
                    mma_tf32(acc[mt][nt][0], acc[mt][nt][1], acc[mt][nt][2], acc[mt][nt][3],
                             a[mt][0], a[mt][1], a[mt][2], a[mt][3], bf[nt][0], bf[nt][1]);
        }
        __syncthreads();
    }

    // epilogue: scatter window-reverse to (B, C, H, W) + bias
#pragma unroll
    for (int mt = 0; mt < 4; mt++) {
#pragma unroll
        for (int nt = 0; nt < 4; nt++) {
            int row0 = warpM * 64 + mt * 16 + g;
            int col0 = warpN * 32 + nt * 8 + tg * 2;
#pragma unroll
            for (int e = 0; e < 4; e++) {
                int row = row0 + ((e >= 2) ? 8 : 0);
                int col = col0 + (e & 1);
                int c = obase + col;
                float v = acc[mt][nt][e] + pb[c];
                int wb = wb0 + (row >> 6), tt = row & 63;
                int b = wb >> 6, wy = (wb >> 3) & 7, wx = wb & 7;
                int h = wy * 8 + (tt >> 3), w = wx * 8 + (tt & 7);
                out[(b * CDIM + c) * 4096 + h * 64 + w] = v;
            }
        }
    }
}

// ---------------------------------------------------------------------------
extern "C" void kernel_launch(void* const* d_in, const int* in_sizes, int n_in,
                              void* d_out, int out_size) {
    const float* x      = (const float*)d_in[0];
    const float* qkv_w  = (const float*)d_in[1];
    const float* qkv_b  = (const float*)d_in[2];
    const float* proj_w = (const float*)d_in[3];
    const float* proj_b = (const float*)d_in[4];
    const float* rpb    = (const float*)d_in[5];
    const int*   rel    = (const int*)d_in[6];
    float* out = (float*)d_out;

    qkv_kernel<<<dim3(9, 512), 256>>>(x, qkv_w, qkv_b);
    attn_kernel<<<dim3(12, 1024), 64>>>(rpb, rel);
    proj_kernel<<<dim3(3, 512), 256>>>(proj_w, proj_b, out);
}

// round 15
// speedup vs baseline: 1.2605x; 1.2605x over previous
#include <cuda_runtime.h>
#include <cuda_bf16.h>

// ---------------------------------------------------------------------------
// W-MSA: windowed multi-head self-attention (Swin block)
// B=16, C=384, H=W=64, window 8x8 (N=64), heads=12, hd=32, B_=1024 windows.
// tf32 mma.sync GEMMs for QKV + proj; fp32 SIMT fused attention.
// R2: k-major X smem (float4 gather/store), uint4 tile stores, coalesced
//     transposed bias table, float4 LDS in attention.
// ---------------------------------------------------------------------------

#define NWIN   1024
#define NHEAD  12
#define HD     32
#define NTOK   64
#define CDIM   384

__device__ float g_q[NWIN * NHEAD * NTOK * HD];
__device__ float g_k[NWIN * NHEAD * NTOK * HD];
__device__ float g_v[NWIN * NHEAD * NTOK * HD];
__device__ float g_ao[NWIN * NTOK * CDIM];
__device__ float g_biasT[NHEAD * NTOK * NTOK];   // [head][m][t]

__device__ __forceinline__ unsigned f2tf32(float f) {
    unsigned u;
    asm("cvt.rna.tf32.f32 %0, %1;" : "=r"(u) : "f"(f));
    return u;
}

__device__ __forceinline__ void mma_tf32(float& c0, float& c1, float& c2, float& c3,
                                         unsigned a0, unsigned a1, unsigned a2, unsigned a3,
                                         unsigned b0, unsigned b1) {
    asm volatile(
        "mma.sync.aligned.m16n8k8.row.col.f32.tf32.tf32.f32 "
        "{%0,%1,%2,%3}, {%4,%5,%6,%7}, {%8,%9}, {%0,%1,%2,%3};\n"
        : "+f"(c0), "+f"(c1), "+f"(c2), "+f"(c3)
        : "r"(a0), "r"(a1), "r"(a2), "r"(a3), "r"(b0), "r"(b1));
}

// ---------------------------------------------------------------------------
// Kernel 0: bias table  g_biasT[head][m][t] = rpb[rel[t,m]][head]
// ---------------------------------------------------------------------------
__global__ void bias_kernel(const float* __restrict__ rpb, const int* __restrict__ rel) {
    const int head = blockIdx.x;
    for (int i = threadIdx.x; i < NTOK * NTOK; i += blockDim.x) {
        int m = i >> 6, t = i & 63;
        g_biasT[head * NTOK * NTOK + m * NTOK + t] = rpb[rel[t * NTOK + m] * NHEAD + head];
    }
}

// ---------------------------------------------------------------------------
// Kernel 1: QKV = gather(x) @ qkv_w^T + qkv_b
// BM=128 (2 windows), BN=128, BK=32.  256 threads = 8 warps (2M x 4N).
// sX is k-major [32][128+8]: float4 gather LDG + STS.128, conflict-free frags.
// ---------------------------------------------------------------------------
#define XPAD 136
__global__ __launch_bounds__(256) void qkv_kernel(const float* __restrict__ x,
                                                  const float* __restrict__ qkv_w,
                                                  const float* __restrict__ qkv_b) {
    __shared__ unsigned sX[32 * XPAD];   // [k][row]
    __shared__ unsigned sW[128 * 36];    // [o][k]

    const int tid  = threadIdx.x;
    const int warp = tid >> 5, lane = tid & 31;
    const int g = lane >> 2, tg = lane & 3;
    const int warpM = warp >> 2;   // 0..1
    const int warpN = warp & 3;    // 0..3

    const int pair  = blockIdx.y;        // 0..511
    const int obase = blockIdx.x * 128;  // 0..1151
    const int wb0   = pair * 2;

    // precompute gather geometry for this thread's 4 float4 slots
    // slot s: k = s>>5, row0 = (s&31)*4
    int xoff[4];  // gmem offset (excluding k term) for each j
    int kidx[4];
#pragma unroll
    for (int j = 0; j < 4; j++) {
        int s = tid + j * 256;
        int k = s >> 5;
        int row0 = (s & 31) * 4;
        int wb = wb0 + (row0 >> 6);
        int tt = row0 & 63;
        int b = wb >> 6, wy = (wb >> 3) & 7, wx = wb & 7;
        int h = wy * 8 + (tt >> 3), w = wx * 8 + (tt & 7);
        xoff[j] = b * CDIM * 4096 + h * 64 + w;
        kidx[j] = k;
    }

    float acc[4][4][4];
#pragma unroll
    for (int i = 0; i < 4; i++)
#pragma unroll
        for (int j = 0; j < 4; j++)
#pragma unroll
            for (int e = 0; e < 4; e++) acc[i][j][e] = 0.f;

    for (int kc = 0; kc < 12; kc++) {
        const int k0 = kc * 32;
        // --- X tile: float4 gather, STS.128 into k-major layout ---
#pragma unroll
        for (int j = 0; j < 4; j++) {
            const float4 v4 = *(const float4*)(x + xoff[j] + (k0 + kidx[j]) * 4096);
            int s = tid + j * 256;
            unsigned* p = &sX[kidx[j] * XPAD + (s & 31) * 4];
            uint4 u;
            u.x = f2tf32(v4.x); u.y = f2tf32(v4.y); u.z = f2tf32(v4.z); u.w = f2tf32(v4.w);
            *(uint4*)p = u;
        }
        // --- W tile: float4 LDG + uint4 STS, [o][k] pad 36 ---
#pragma unroll
        for (int i = tid; i < 1024; i += 256) {
            int row = i >> 3, kq = i & 7;
            const float4 v4 = *(const float4*)(qkv_w + (obase + row) * CDIM + k0 + kq * 4);
            uint4 u;
            u.x = f2tf32(v4.x); u.y = f2tf32(v4.y); u.z = f2tf32(v4.z); u.w = f2tf32(v4.w);
            *(uint4*)&sW[row * 36 + kq * 4] = u;
        }
        __syncthreads();

#pragma unroll
        for (int ks = 0; ks < 4; ks++) {
            const int ko = ks * 8;
            unsigned a[4][4], bf[4][2];
#pragma unroll
            for (int mt = 0; mt < 4; mt++) {
                int rb = warpM * 64 + mt * 16;
                const unsigned* base = &sX[(ko + tg) * XPAD + rb + g];
                a[mt][0] = base[0];
                a[mt][1] = base[8];
                a[mt][2] = base[4 * XPAD];
                a[mt][3] = base[4 * XPAD + 8];
            }
#pragma unroll
            for (int nt = 0; nt < 4; nt++) {
                int nb = warpN * 32 + nt * 8;
                const unsigned* base = &sW[(nb + g) * 36 + ko + tg];
                bf[nt][0] = base[0];
                bf[nt][1] = base[4];
            }
#pragma unroll
            for (int mt = 0; mt < 4; mt++)
#pragma unroll
                for (int nt = 0; nt < 4; nt++)
                    mma_tf32(acc[mt][nt][0], acc[mt][nt][1], acc[mt][nt][2], acc[mt][nt][3],
                             a[mt][0], a[mt][1], a[mt][2], a[mt][3], bf[nt][0], bf[nt][1]);
        }
        __syncthreads();
    }

    const float SCALE = 0.17677669529663687f;  // 1/sqrt(32)
#pragma unroll
    for (int mt = 0; mt < 4; mt++) {
#pragma unroll
        for (int nt = 0; nt < 4; nt++) {
            int row0 = warpM * 64 + mt * 16 + g;
            int col0 = warpN * 32 + nt * 8 + tg * 2;
#pragma unroll
            for (int e = 0; e < 4; e++) {
                int row = row0 + ((e >= 2) ? 8 : 0);
                int col = col0 + (e & 1);
                int o = obase + col;
                float v = acc[mt][nt][e] + qkv_b[o];
                int which = o / CDIM;
                int rem = o - which * CDIM;
                int head = rem >> 5, d = rem & 31;
                int wb = wb0 + (row >> 6), tt = row & 63;
                if (which == 0) v *= SCALE;
                float* dst = (which == 0) ? g_q : ((which == 1) ? g_k : g_v);
                dst[((wb * NHEAD + head) * NTOK + tt) * HD + d] = v;
            }
        }
    }
}

// ---------------------------------------------------------------------------
// Kernel 2: per-(window, head) attention.  64 threads; thread t = query row t.
// ---------------------------------------------------------------------------
__global__ __launch_bounds__(64) void attn_kernel() {
    __shared__ float sK[NTOK * HD];
    __shared__ float sV[NTOK * HD];
    const int head = blockIdx.x;
    const int wb   = blockIdx.y;
    const int t    = threadIdx.x;

    const int base = (wb * NHEAD + head) * NTOK * HD;
    const float4* kp = (const float4*)(g_k + base);
    const float4* vp = (const float4*)(g_v + base);
#pragma unroll
    for (int i = t; i < NTOK * HD / 4; i += 64) {
        ((float4*)sK)[i] = kp[i];
        ((float4*)sV)[i] = vp[i];
    }

    float4 q[8];
    const float4* qp = (const float4*)(g_q + base + t * HD);
#pragma unroll
    for (int i = 0; i < 8; i++) q[i] = qp[i];
    __syncthreads();

    const float* bT = g_biasT + head * NTOK * NTOK + t;  // [m][t] coalesced in t
    float S[NTOK];
#pragma unroll
    for (int m = 0; m < NTOK; m++) {
        float acc = bT[m * NTOK];
        const float4* Kr = (const float4*)(sK + m * HD);
#pragma unroll
        for (int i = 0; i < 8; i++) {
            float4 kv = Kr[i];
            acc = fmaf(q[i].x, kv.x, acc);
            acc = fmaf(q[i].y, kv.y, acc);
            acc = fmaf(q[i].z, kv.z, acc);
            acc = fmaf(q[i].w, kv.w, acc);
        }
        S[m] = acc;
    }

    float mx = S[0];
#pragma unroll
    for (int m = 1; m < NTOK; m++) mx = fmaxf(mx, S[m]);
    float sum = 0.f;
#pragma unroll
    for (int m = 0; m < NTOK; m++) { S[m] = __expf(S[m] - mx); sum += S[m]; }
    const float inv = 1.0f / sum;

    float4 out[8];
#pragma unroll
    for (int i = 0; i < 8; i++) out[i] = make_float4(0.f, 0.f, 0.f, 0.f);
#pragma unroll
    for (int m = 0; m < NTOK; m++) {
        float p = S[m];
        const float4* Vr = (const float4*)(sV + m * HD);
#pragma unroll
        for (int i = 0; i < 8; i++) {
            float4 vv = Vr[i];
            out[i].x = fmaf(p, vv.x, out[i].x);
            out[i].y = fmaf(p, vv.y, out[i].y);
            out[i].z = fmaf(p, vv.z, out[i].z);
            out[i].w = fmaf(p, vv.w, out[i].w);
        }
    }

    float* dst = g_ao + (wb * NTOK + t) * CDIM + head * HD;
#pragma unroll
    for (int i = 0; i < 8; i++) {
        float4 v = make_float4(out[i].x * inv, out[i].y * inv, out[i].z * inv, out[i].w * inv);
        *(float4*)(dst + i * 4) = v;
    }
}

// ---------------------------------------------------------------------------
// Kernel 3: out = g_ao @ proj_w^T + proj_b, scatter window-reverse to NCHW.
// ---------------------------------------------------------------------------
__global__ __launch_bounds__(256) void proj_kernel(const float* __restrict__ pw,
                                                   const float* __restrict__ pb,
                                                   float* __restrict__ out) {
    __shared__ unsigned sA[128 * 36];
    __shared__ unsigned sW[128 * 36];

    const int tid  = threadIdx.x;
    const int warp = tid >> 5, lane = tid & 31;
    const int g = lane >> 2, tg = lane & 3;
    const int warpM = warp >> 2;
    const int warpN = warp & 3;

    const int pair  = blockIdx.y;
    const int obase = blockIdx.x * 128;
    const int wb0   = pair * 2;

    float acc[4][4][4];
#pragma unroll
    for (int i = 0; i < 4; i++)
#pragma unroll
        for (int j = 0; j < 4; j++)
#pragma unroll
            for (int e = 0; e < 4; e++) acc[i][j][e] = 0.f;

    for (int kc = 0; kc < 12; kc++) {
        const int k0 = kc * 32;
#pragma unroll
        for (int i = tid; i < 1024; i += 256) {
            int row = i >> 3, kq = i & 7;
            const float4 v4 = *(const float4*)(g_ao + (pair * 128 + row) * CDIM + k0 + kq * 4);
            uint4 u;
            u.x = f2tf32(v4.x); u.y = f2tf32(v4.y); u.z = f2tf32(v4.z); u.w = f2tf32(v4.w);
            *(uint4*)&sA[row * 36 + kq * 4] = u;
        }
#pragma unroll
        for (int i = tid; i < 1024; i += 256) {
            int row = i >> 3, kq = i & 7;
            const float4 v4 = *(const float4*)(pw + (obase + row) * CDIM + k0 + kq * 4);
            uint4 u;
            u.x = f2tf32(v4.x); u.y = f2tf32(v4.y); u.z = f2tf32(v4.z); u.w = f2tf32(v4.w);
            *(uint4*)&sW[row * 36 + kq * 4] = u;
        }
        __syncthreads();

#pragma unroll
        for (int ks = 0; ks < 4; ks++) {
            const int ko = ks * 8;
            unsigned a[4][4], bf[4][2];
#pragma unroll
            for (int mt = 0; mt < 4; mt++) {
                int rb = warpM * 64 + mt * 16;
                const unsigned* base = &sA[(rb + g) * 36 + ko + tg];
                a[mt][0] = base[0];
                a[mt][1] = base[8 * 36];
                a[mt][2] = base[4];
                a[mt][3] = base[8 * 36 + 4];
            }
#pragma unroll
            for (int nt = 0; nt < 4; nt++) {
                int nb = warpN * 32 + nt * 8;
                const unsigned* base = &sW[(nb + g) * 36 + ko + tg];
                bf[nt][0] = base[0];
                bf[nt][1] = base[4];
            }
#pragma unroll
            for (int mt = 0; mt < 4; mt++)
#pragma unroll
                for (int nt = 0; nt < 4; nt++)
                    mma_tf32(acc[mt][nt][0], acc[mt][nt][1], acc[mt][nt][2], acc[mt][nt][3],
                             a[mt][0], a[mt][1], a[mt][2], a[mt][3], bf[nt][0], bf[nt][1]);
        }
        __syncthreads();
    }

#pragma unroll
    for (int mt = 0; mt < 4; mt++) {
#pragma unroll
        for (int nt = 0; nt < 4; nt++) {
            int row0 = warpM * 64 + mt * 16 + g;
            int col0 = warpN * 32 + nt * 8 + tg * 2;
#pragma unroll
            for (int e = 0; e < 4; e++) {
                int row = row0 + ((e >= 2) ? 8 : 0);
                int col = col0 + (e & 1);
                int c = obase + col;
                float v = acc[mt][nt][e] + pb[c];
                int wb = wb0 + (row >> 6), tt = row & 63;
                int b = wb >> 6, wy = (wb >> 3) & 7, wx = wb & 7;
                int h = wy * 8 + (tt >> 3), w = wx * 8 + (tt & 7);
                out[(b * CDIM + c) * 4096 + h * 64 + w] = v;
            }
        }
    }
}

// ---------------------------------------------------------------------------
extern "C" void kernel_launch(void* const* d_in, const int* in_sizes, int n_in,
                              void* d_out, int out_size) {
    const float* x      = (const float*)d_in[0];
    const float* qkv_w  = (const float*)d_in[1];
    const float* qkv_b  = (const float*)d_in[2];
    const float* proj_w = (const float*)d_in[3];
    const float* proj_b = (const float*)d_in[4];
    const float* rpb    = (const float*)d_in[5];
    const int*   rel    = (const int*)d_in[6];
    float* out = (float*)d_out;

    bias_kernel<<<NHEAD, 256>>>(rpb, rel);
    qkv_kernel<<<dim3(9, 512), 256>>>(x, qkv_w, qkv_b);
    attn_kernel<<<dim3(NHEAD, NWIN), 64>>>();
    proj_kernel<<<dim3(3, 512), 256>>>(proj_w, proj_b, out);
}